// round 7
// baseline (speedup 1.0000x reference)
#include <cuda_runtime.h>
#include <cuda_fp16.h>
#include <cuda_fp8.h>

#define N_SEL   8192
#define N_FEAT  256
#define K_SUB   256
#define N_PERS  4
#define E_FULL  262144
#define E_RAW   262144
#define N_TOTAL 8192
#define EPSILON 0.5f
#define SCREEN  0.35f
#define LAMB1   0.5f

#define MAIN_BLOCKS 592                 // 4 per SM * 148 SMs (fully resident)
#define NT          (MAIN_BLOCKS * 256) // 151552 threads
#define NWARP       (NT / 32)           // 4736 warps
#define MAIN_ITERS  56                  // 56*NWARP >= E_FULL
#define OUT_F4      16777216            // 8192*8192/4
#define PREP_FILL_N 3670016             // 262144 threads * 14 float4 (56 MB)
#define FILL_MAIN   (OUT_F4 - PREP_FILL_N)   // 13107200 float4 (200 MB)

// ---------------- device scratch (no device allocations allowed) ----------------
__device__ uint2    g_qtab[N_SEL * 32];   // fp8 e4m3 table: 256 B/row (2 MB)
__device__ float4   g_rinv4[N_SEL];       // per-node {rinv_p0..p3}
__device__ float    g_nodew[N_SEL];       // score[batch[i]] * LAMB1
__device__ unsigned g_bitmap[(size_t)N_SEL * N_SEL / 32];  // dedup, lazily cleared
__device__ int      g_nhits;
__device__ int      g_hit_off[E_FULL];
__device__ float    g_hit_val[E_FULL];
__device__ int      g_hit_word[E_FULL];

// ---------------- helpers ----------------
__device__ __forceinline__ unsigned short f2_to_fp8x2(float a, float b) {
    float2 v = make_float2(a, b);
    return __nv_cvt_float2_to_fp8x2(v, __NV_SATFINITE, __NV_E4M3);
}
__device__ __forceinline__ __half2 fp8x2_to_h2(unsigned short u) {
    __half2_raw r = __nv_cvt_fp8x2_to_halfraw2((__nv_fp8x2_storage_t)u, __NV_E4M3);
    return *reinterpret_cast<__half2*>(&r);
}

// ---------------- prep: quant + rinv + 56MB fill (blocks 0..1023) | score (1024) ----
__global__ void __launch_bounds__(256) prep_kernel(const float* __restrict__ x,
                                                   const float* __restrict__ mw,
                                                   const float* __restrict__ sc,
                                                   const int* __restrict__ belong,
                                                   const int* __restrict__ batch,
                                                   float4* __restrict__ out4) {
    if (blockIdx.x == 1024) {
        __shared__ float s_sc[K_SUB];
        __shared__ int   s_bl[K_SUB];
        __shared__ float s_sum[K_SUB];
        __shared__ float s_norm[K_SUB];
        int t = threadIdx.x;
        s_sc[t] = sc[t];
        s_bl[t] = belong[t];
        __syncthreads();
        float s = 0.f;
        #pragma unroll 8
        for (int k = 0; k < K_SUB; k++)
            s += (s_bl[k] == t) ? s_sc[k] : 0.f;
        s_sum[t] = s;
        __syncthreads();
        s_norm[t] = s_sc[t] / s_sum[s_bl[t]];
        if (t == 0) g_nhits = 0;
        __syncthreads();
        for (int i = t; i < N_SEL; i += K_SUB)
            g_nodew[i] = s_norm[batch[i]] * LAMB1;
        return;
    }

    int gtid = blockIdx.x * 256 + threadIdx.x;     // 0..262143
    int lane = threadIdx.x & 31;
    int n = gtid >> 5;                             // node, 0..8191

    // ---- fire-and-forget zero-fill of out tail (hidden under latency chain) ----
    {
        const float4 z = make_float4(0.f, 0.f, 0.f, 0.f);
        int base = FILL_MAIN + gtid;
        #pragma unroll
        for (int k = 0; k < 14; k++)
            __stcs(out4 + base + k * 262144, z);
    }

    // ---- per-node (warp per node): fp8 quant + 4 inverse weighted norms ----
    const float4* xr = reinterpret_cast<const float4*>(x + (size_t)n * N_FEAT);
    float4 a = __ldg(xr + 2 * lane);               // dims 8*lane .. 8*lane+3
    float4 b = __ldg(xr + 2 * lane + 1);           // dims 8*lane+4 ..

    unsigned lo = (unsigned)f2_to_fp8x2(a.x, a.y) | ((unsigned)f2_to_fp8x2(a.z, a.w) << 16);
    unsigned hi = (unsigned)f2_to_fp8x2(b.x, b.y) | ((unsigned)f2_to_fp8x2(b.z, b.w) << 16);
    g_qtab[n * 32 + lane] = make_uint2(lo, hi);

    float sq[8] = {a.x * a.x, a.y * a.y, a.z * a.z, a.w * a.w,
                   b.x * b.x, b.y * b.y, b.z * b.z, b.w * b.w};

    const float4* mw4 = reinterpret_cast<const float4*>(mw);
    float acc[N_PERS];
    #pragma unroll
    for (int p = 0; p < N_PERS; p++) {
        float4 wa = __ldg(mw4 + p * 64 + 2 * lane);
        float4 wb = __ldg(mw4 + p * 64 + 2 * lane + 1);
        acc[p] = sq[0] * wa.x * wa.x + sq[1] * wa.y * wa.y
               + sq[2] * wa.z * wa.z + sq[3] * wa.w * wa.w
               + sq[4] * wb.x * wb.x + sq[5] * wb.y * wb.y
               + sq[6] * wb.z * wb.z + sq[7] * wb.w * wb.w;
    }

    // 6-shuffle multi-value reduction: lane c (c=lane&3) ends with total of acc_c
    bool o1 = lane & 1;
    float u0 = o1 ? acc[0] : acc[1];
    float v0 = (o1 ? acc[1] : acc[0]) + __shfl_xor_sync(0xffffffffu, u0, 1);
    float u1 = o1 ? acc[2] : acc[3];
    float v1 = (o1 ? acc[3] : acc[2]) + __shfl_xor_sync(0xffffffffu, u1, 1);
    bool o2 = lane & 2;
    float tt = o2 ? v0 : v1;
    float w  = (o2 ? v1 : v0) + __shfl_xor_sync(0xffffffffu, tt, 2);
    w += __shfl_xor_sync(0xffffffffu, w, 4);
    w += __shfl_xor_sync(0xffffffffu, w, 8);
    w += __shfl_xor_sync(0xffffffffu, w, 16);

    if (lane < 4)
        reinterpret_cast<float*>(g_rinv4)[4 * n + lane] = 1.0f / (sqrtf(w) + 1e-12f);
}

// ---------------- rare exact path: fp32 recompute + dedup + hit record ----------------
__device__ __noinline__ void exact_edge(int i, int j, int lane,
                                        const float* __restrict__ x,
                                        const float* __restrict__ mw,
                                        const int* __restrict__ smap) {
    const float4* xi = reinterpret_cast<const float4*>(x + (size_t)i * N_FEAT);
    const float4* xj = reinterpret_cast<const float4*>(x + (size_t)j * N_FEAT);
    float4 a0 = __ldg(xi + 2 * lane), a1 = __ldg(xi + 2 * lane + 1);
    float4 b0 = __ldg(xj + 2 * lane), b1 = __ldg(xj + 2 * lane + 1);
    float pr[8] = {a0.x * b0.x, a0.y * b0.y, a0.z * b0.z, a0.w * b0.w,
                   a1.x * b1.x, a1.y * b1.y, a1.z * b1.z, a1.w * b1.w};

    const float4* mw4 = reinterpret_cast<const float4*>(mw);
    float f[N_PERS];
    #pragma unroll
    for (int p = 0; p < N_PERS; p++) {
        float4 wa = __ldg(mw4 + p * 64 + 2 * lane);
        float4 wb = __ldg(mw4 + p * 64 + 2 * lane + 1);
        f[p] = pr[0] * wa.x * wa.x + pr[1] * wa.y * wa.y
             + pr[2] * wa.z * wa.z + pr[3] * wa.w * wa.w
             + pr[4] * wb.x * wb.x + pr[5] * wb.y * wb.y
             + pr[6] * wb.z * wb.z + pr[7] * wb.w * wb.w;
    }
    #pragma unroll
    for (int p = 0; p < N_PERS; p++)
        #pragma unroll
        for (int o = 16; o > 0; o >>= 1)
            f[p] += __shfl_xor_sync(0xffffffffu, f[p], o);

    if (lane == 0) {
        float4 ri = g_rinv4[i];
        float4 rj = g_rinv4[j];
        float sim = 0.25f * (f[0] * ri.x * rj.x + f[1] * ri.y * rj.y
                           + f[2] * ri.z * rj.z + f[3] * ri.w * rj.w);
        if (sim > EPSILON) {
            size_t idx = (size_t)i * N_SEL + j;
            unsigned bit = 1u << (idx & 31u);
            int word = (int)(idx >> 5);
            unsigned old = atomicOr(&g_bitmap[word], bit);
            if (!(old & bit)) {
                int slot = atomicAdd(&g_nhits, 1);
                g_hit_off[slot]  = __ldg(smap + i) * N_TOTAL + __ldg(smap + j);
                g_hit_val[slot]  = sim * g_nodew[i];
                g_hit_word[slot] = word;
            }
        }
    }
}

// ---------------- main: interleaved zero-fill (200 MB) + fp8 edge screen ----------------
__global__ void __launch_bounds__(256, 4) main_kernel(const float* __restrict__ x,
                                                      const float* __restrict__ mw,
                                                      const int* __restrict__ fe,
                                                      const int* __restrict__ smap,
                                                      float4* __restrict__ out4) {
    int tidg = blockIdx.x * 256 + threadIdx.x;     // 0..NT-1
    int lane = threadIdx.x & 31;
    int warp = tidg >> 5;                          // 0..NWARP-1

    // squared weights in half2, lane's 8 dims x 4 perspectives (16 regs)
    __half2 w2r[N_PERS][4];
    {
        const float4* mw4 = reinterpret_cast<const float4*>(mw);
        #pragma unroll
        for (int p = 0; p < N_PERS; p++) {
            float4 wa = __ldg(mw4 + p * 64 + 2 * lane);
            float4 wb = __ldg(mw4 + p * 64 + 2 * lane + 1);
            w2r[p][0] = __floats2half2_rn(wa.x * wa.x, wa.y * wa.y);
            w2r[p][1] = __floats2half2_rn(wa.z * wa.z, wa.w * wa.w);
            w2r[p][2] = __floats2half2_rn(wb.x * wb.x, wb.y * wb.y);
            w2r[p][3] = __floats2half2_rn(wb.z * wb.z, wb.w * wb.w);
        }
    }

    const float4 z = make_float4(0.f, 0.f, 0.f, 0.f);
    int fidx = tidg;

    // pipeline: preload iteration-0 edge indices
    int e0 = warp;
    int i_n = (e0 < E_FULL) ? __ldg(fe + e0) : 0;
    int j_n = (e0 < E_FULL) ? __ldg(fe + E_FULL + e0) : 0;

    for (int it = 0; it < MAIN_ITERS; it++) {
        // ---- two streaming zero-stores (hidden under edge load latency) ----
        if (fidx < FILL_MAIN) __stcs(out4 + fidx, z);
        int f2i = fidx + NT;
        if (f2i < FILL_MAIN) __stcs(out4 + f2i, z);
        fidx += 2 * NT;

        int e = warp + it * NWARP;
        if (e >= E_FULL) continue;
        int i = i_n, j = j_n;

        // kick off this edge's table loads first (longest chain)
        uint2 qi = __ldg(g_qtab + i * 32 + lane);
        uint2 qj = __ldg(g_qtab + j * 32 + lane);

        // prefetch next iteration's indices (breaks fe->qtab serial chain)
        int en = e + NWARP;
        if (en < E_FULL) {
            i_n = __ldg(fe + en);
            j_n = __ldg(fe + E_FULL + en);
        }

        // hw fp8x2 -> half2 decode (8 cvts)
        __half2 hi0 = fp8x2_to_h2((unsigned short)(qi.x & 0xffffu));
        __half2 hi1 = fp8x2_to_h2((unsigned short)(qi.x >> 16));
        __half2 hi2 = fp8x2_to_h2((unsigned short)(qi.y & 0xffffu));
        __half2 hi3 = fp8x2_to_h2((unsigned short)(qi.y >> 16));
        __half2 hj0 = fp8x2_to_h2((unsigned short)(qj.x & 0xffffu));
        __half2 hj1 = fp8x2_to_h2((unsigned short)(qj.x >> 16));
        __half2 hj2 = fp8x2_to_h2((unsigned short)(qj.y & 0xffffu));
        __half2 hj3 = fp8x2_to_h2((unsigned short)(qj.y >> 16));

        __half2 pr0 = __hmul2(hi0, hj0);
        __half2 pr1 = __hmul2(hi1, hj1);
        __half2 pr2 = __hmul2(hi2, hj2);
        __half2 pr3 = __hmul2(hi3, hj3);

        __half2 a0 = __hmul2(pr0, w2r[0][0]);
        __half2 a1 = __hmul2(pr0, w2r[1][0]);
        __half2 a2 = __hmul2(pr0, w2r[2][0]);
        __half2 a3 = __hmul2(pr0, w2r[3][0]);
        a0 = __hfma2(pr1, w2r[0][1], a0); a1 = __hfma2(pr1, w2r[1][1], a1);
        a2 = __hfma2(pr1, w2r[2][1], a2); a3 = __hfma2(pr1, w2r[3][1], a3);
        a0 = __hfma2(pr2, w2r[0][2], a0); a1 = __hfma2(pr2, w2r[1][2], a1);
        a2 = __hfma2(pr2, w2r[2][2], a2); a3 = __hfma2(pr2, w2r[3][2], a3);
        a0 = __hfma2(pr3, w2r[0][3], a0); a1 = __hfma2(pr3, w2r[1][3], a1);
        a2 = __hfma2(pr3, w2r[2][3], a2); a3 = __hfma2(pr3, w2r[3][3], a3);

        float f0 = __low2float(a0) + __high2float(a0);
        float f1 = __low2float(a1) + __high2float(a1);
        float f2 = __low2float(a2) + __high2float(a2);
        float f3 = __low2float(a3) + __high2float(a3);

        // 6-shuffle multi-value reduction -> lane class c=lane&3 holds total of acc_c
        bool o1 = lane & 1;
        float u0 = o1 ? f0 : f1;
        float v0 = (o1 ? f1 : f0) + __shfl_xor_sync(0xffffffffu, u0, 1);
        float u1 = o1 ? f2 : f3;
        float v1 = (o1 ? f3 : f2) + __shfl_xor_sync(0xffffffffu, u1, 1);
        bool o2 = lane & 2;
        float tt = o2 ? v0 : v1;
        float w  = (o2 ? v1 : v0) + __shfl_xor_sync(0xffffffffu, tt, 2);
        w += __shfl_xor_sync(0xffffffffu, w, 4);
        w += __shfl_xor_sync(0xffffffffu, w, 8);
        w += __shfl_xor_sync(0xffffffffu, w, 16);

        int c = lane & 3;
        float ri = __ldg(reinterpret_cast<const float*>(g_rinv4) + 4 * i + c);
        float rj = __ldg(reinterpret_cast<const float*>(g_rinv4) + 4 * j + c);
        float s = w * ri * rj;
        s += __shfl_xor_sync(0xffffffffu, s, 1);
        s += __shfl_xor_sync(0xffffffffu, s, 2);
        float simA = 0.25f * __shfl_sync(0xffffffffu, s, 0);

        if (simA > SCREEN && i != j)
            exact_edge(i, j, lane, x, mw, smap);   // warp-uniform rare path
    }
}

// ---------------- scatter: raw edges + hits + lazy bitmap clear ----------------
__global__ void scatter_kernel(const int* __restrict__ re, float* __restrict__ out) {
    int t = blockIdx.x * blockDim.x + threadIdx.x;   // exactly E_RAW threads
    int r = __ldg(re + t);
    int c = __ldg(re + E_RAW + t);
    atomicAdd(out + (size_t)r * N_TOTAL + c, 1.0f - LAMB1);
    if (t < g_nhits) {
        atomicAdd(out + (size_t)g_hit_off[t], g_hit_val[t]);
        g_bitmap[g_hit_word[t]] = 0;                 // keep replay-deterministic
    }
}

// ---------------- launch ----------------
extern "C" void kernel_launch(void* const* d_in, const int* in_sizes, int n_in,
                              void* d_out, int out_size) {
    const float* x      = (const float*)d_in[0];   // [8192, 256]
    const float* mw     = (const float*)d_in[1];   // [4, 256]
    const int*   batch  = (const int*)  d_in[2];   // [8192]
    const int*   smap   = (const int*)  d_in[3];   // [8192]
    const int*   belong = (const int*)  d_in[4];   // [256]
    const float* score  = (const float*)d_in[5];   // [256]
    const int*   fe     = (const int*)  d_in[6];   // [2, 262144]
    const int*   re     = (const int*)  d_in[7];   // [2, 262144]
    float* out = (float*)d_out;                    // [8192, 8192]

    prep_kernel<<<1025, 256>>>(x, mw, score, belong, batch,
                               reinterpret_cast<float4*>(out));
    main_kernel<<<MAIN_BLOCKS, 256>>>(x, mw, fe, smap,
                                      reinterpret_cast<float4*>(out));
    scatter_kernel<<<E_RAW / 256, 256>>>(re, out);
}

// round 9
// speedup vs baseline: 1.1587x; 1.1587x over previous
#include <cuda_runtime.h>
#include <cuda_fp16.h>
#include <cuda_fp8.h>

#define N_SEL   8192
#define N_FEAT  256
#define K_SUB   256
#define N_PERS  4
#define E_FULL  262144
#define E_RAW   262144
#define N_TOTAL 8192
#define EPSILON 0.5f
#define SCREEN  0.35f
#define LAMB1   0.5f

#define MAIN_BLOCKS 592                 // 4 per SM * 148 SMs (fully resident)
#define NT          (MAIN_BLOCKS * 256) // 151552 threads
#define NWARP       (NT / 32)           // 4736 warps
#define MAIN_ITERS  56                  // 56*NWARP >= E_FULL ; 56*2*NT >= OUT_F4
#define OUT_F4      16777216            // 8192*8192/4

// ---------------- device scratch (no device allocations allowed) ----------------
__device__ uint2    g_qtab[N_SEL * 32];   // fp8 e4m3 table: 256 B/row (2 MB)
__device__ float4   g_rinv4[N_SEL];       // per-node {rinv_p0..p3}
__device__ float    g_nodew[N_SEL];       // score[batch[i]] * LAMB1
__device__ unsigned g_bitmap[(size_t)N_SEL * N_SEL / 32];  // dedup, lazily cleared
__device__ int      g_nhits;
__device__ int      g_hit_off[E_FULL];
__device__ float    g_hit_val[E_FULL];
__device__ int      g_hit_word[E_FULL];

// ---------------- helpers ----------------
__device__ __forceinline__ unsigned short f2_to_fp8x2(float a, float b) {
    float2 v = make_float2(a, b);
    return __nv_cvt_float2_to_fp8x2(v, __NV_SATFINITE, __NV_E4M3);
}
__device__ __forceinline__ __half2 fp8x2_to_h2(unsigned short u) {
    __half2_raw r = __nv_cvt_fp8x2_to_halfraw2((__nv_fp8x2_storage_t)u, __NV_E4M3);
    return *reinterpret_cast<__half2*>(&r);
}

// ---------------- per-node quant + weighted-norm accumulators ----------------
__device__ __forceinline__ void quant_and_acc(int n, int lane,
                                              const float* __restrict__ x,
                                              const float4* __restrict__ mw4,
                                              float4 a, float4 b,
                                              float* acc) {
    unsigned lo = (unsigned)f2_to_fp8x2(a.x, a.y) | ((unsigned)f2_to_fp8x2(a.z, a.w) << 16);
    unsigned hi = (unsigned)f2_to_fp8x2(b.x, b.y) | ((unsigned)f2_to_fp8x2(b.z, b.w) << 16);
    g_qtab[n * 32 + lane] = make_uint2(lo, hi);

    float sq[8] = {a.x * a.x, a.y * a.y, a.z * a.z, a.w * a.w,
                   b.x * b.x, b.y * b.y, b.z * b.z, b.w * b.w};
    #pragma unroll
    for (int p = 0; p < N_PERS; p++) {
        float4 wa = __ldg(mw4 + p * 64 + 2 * lane);
        float4 wb = __ldg(mw4 + p * 64 + 2 * lane + 1);
        acc[p] = sq[0] * wa.x * wa.x + sq[1] * wa.y * wa.y
               + sq[2] * wa.z * wa.z + sq[3] * wa.w * wa.w
               + sq[4] * wb.x * wb.x + sq[5] * wb.y * wb.y
               + sq[6] * wb.z * wb.z + sq[7] * wb.w * wb.w;
    }
}

// 6-shuffle multi-value reduce; afterwards every lane l holds total of acc[l&3]
__device__ __forceinline__ float multi_reduce4(int lane, const float* acc) {
    bool o1 = lane & 1;
    float u0 = o1 ? acc[0] : acc[1];
    float v0 = (o1 ? acc[1] : acc[0]) + __shfl_xor_sync(0xffffffffu, u0, 1);
    float u1 = o1 ? acc[2] : acc[3];
    float v1 = (o1 ? acc[3] : acc[2]) + __shfl_xor_sync(0xffffffffu, u1, 1);
    bool o2 = lane & 2;
    float tt = o2 ? v0 : v1;
    float w  = (o2 ? v1 : v0) + __shfl_xor_sync(0xffffffffu, tt, 2);
    w += __shfl_xor_sync(0xffffffffu, w, 4);
    w += __shfl_xor_sync(0xffffffffu, w, 8);
    w += __shfl_xor_sync(0xffffffffu, w, 16);
    return w;
}

// ---------------- prep: quant + rinv, 2 nodes/warp (blocks 0..511) | score (512) ----
__global__ void __launch_bounds__(256) prep_kernel(const float* __restrict__ x,
                                                   const float* __restrict__ mw,
                                                   const float* __restrict__ sc,
                                                   const int* __restrict__ belong,
                                                   const int* __restrict__ batch) {
    if (blockIdx.x == 512) {
        __shared__ float s_sc[K_SUB];
        __shared__ int   s_bl[K_SUB];
        __shared__ float s_sum[K_SUB];
        __shared__ float s_norm[K_SUB];
        int t = threadIdx.x;
        s_sc[t] = sc[t];
        s_bl[t] = belong[t];
        __syncthreads();
        float s = 0.f;
        #pragma unroll 8
        for (int k = 0; k < K_SUB; k++)
            s += (s_bl[k] == t) ? s_sc[k] : 0.f;
        s_sum[t] = s;
        __syncthreads();
        s_norm[t] = s_sc[t] / s_sum[s_bl[t]];
        if (t == 0) g_nhits = 0;
        __syncthreads();
        for (int i = t; i < N_SEL; i += K_SUB)
            g_nodew[i] = s_norm[batch[i]] * LAMB1;
        return;
    }

    int lane = threadIdx.x & 31;
    int wrp  = (blockIdx.x * 256 + threadIdx.x) >> 5;   // 0..4095
    int n0 = 2 * wrp, n1 = 2 * wrp + 1;

    // 4 independent 128-bit loads up front (MLP 4)
    const float4* xr0 = reinterpret_cast<const float4*>(x + (size_t)n0 * N_FEAT);
    const float4* xr1 = reinterpret_cast<const float4*>(x + (size_t)n1 * N_FEAT);
    float4 a0 = __ldg(xr0 + 2 * lane), b0 = __ldg(xr0 + 2 * lane + 1);
    float4 a1 = __ldg(xr1 + 2 * lane), b1 = __ldg(xr1 + 2 * lane + 1);

    const float4* mw4 = reinterpret_cast<const float4*>(mw);
    float accA[N_PERS], accB[N_PERS];
    quant_and_acc(n0, lane, x, mw4, a0, b0, accA);
    quant_and_acc(n1, lane, x, mw4, a1, b1, accB);

    float wA = multi_reduce4(lane, accA);
    float wB = multi_reduce4(lane, accB);

    if (lane < 4)
        reinterpret_cast<float*>(g_rinv4)[4 * n0 + lane] = 1.0f / (sqrtf(wA) + 1e-12f);
    else if (lane < 8)
        reinterpret_cast<float*>(g_rinv4)[4 * n1 + (lane - 4)] = 1.0f / (sqrtf(wB) + 1e-12f);
}

// ---------------- rare exact path: fp32 recompute + dedup + hit record ----------------
__device__ __noinline__ void exact_edge(int i, int j, int lane,
                                        const float* __restrict__ x,
                                        const float* __restrict__ mw,
                                        const int* __restrict__ smap) {
    const float4* xi = reinterpret_cast<const float4*>(x + (size_t)i * N_FEAT);
    const float4* xj = reinterpret_cast<const float4*>(x + (size_t)j * N_FEAT);
    float4 a0 = __ldg(xi + 2 * lane), a1 = __ldg(xi + 2 * lane + 1);
    float4 b0 = __ldg(xj + 2 * lane), b1 = __ldg(xj + 2 * lane + 1);
    float pr[8] = {a0.x * b0.x, a0.y * b0.y, a0.z * b0.z, a0.w * b0.w,
                   a1.x * b1.x, a1.y * b1.y, a1.z * b1.z, a1.w * b1.w};

    const float4* mw4 = reinterpret_cast<const float4*>(mw);
    float f[N_PERS];
    #pragma unroll
    for (int p = 0; p < N_PERS; p++) {
        float4 wa = __ldg(mw4 + p * 64 + 2 * lane);
        float4 wb = __ldg(mw4 + p * 64 + 2 * lane + 1);
        f[p] = pr[0] * wa.x * wa.x + pr[1] * wa.y * wa.y
             + pr[2] * wa.z * wa.z + pr[3] * wa.w * wa.w
             + pr[4] * wb.x * wb.x + pr[5] * wb.y * wb.y
             + pr[6] * wb.z * wb.z + pr[7] * wb.w * wb.w;
    }
    #pragma unroll
    for (int p = 0; p < N_PERS; p++)
        #pragma unroll
        for (int o = 16; o > 0; o >>= 1)
            f[p] += __shfl_xor_sync(0xffffffffu, f[p], o);

    if (lane == 0) {
        float4 ri = g_rinv4[i];
        float4 rj = g_rinv4[j];
        float sim = 0.25f * (f[0] * ri.x * rj.x + f[1] * ri.y * rj.y
                           + f[2] * ri.z * rj.z + f[3] * ri.w * rj.w);
        if (sim > EPSILON) {
            size_t idx = (size_t)i * N_SEL + j;
            unsigned bit = 1u << (idx & 31u);
            int word = (int)(idx >> 5);
            unsigned old = atomicOr(&g_bitmap[word], bit);
            if (!(old & bit)) {
                int slot = atomicAdd(&g_nhits, 1);
                g_hit_off[slot]  = __ldg(smap + i) * N_TOTAL + __ldg(smap + j);
                g_hit_val[slot]  = sim * g_nodew[i];
                g_hit_word[slot] = word;
            }
        }
    }
}

// ---------------- main: interleaved zero-fill (256 MB) + fp8 edge screen ----------------
__global__ void __launch_bounds__(256, 4) main_kernel(const float* __restrict__ x,
                                                      const float* __restrict__ mw,
                                                      const int* __restrict__ fe,
                                                      const int* __restrict__ smap,
                                                      float4* __restrict__ out4) {
    int tidg = blockIdx.x * 256 + threadIdx.x;     // 0..NT-1
    int lane = threadIdx.x & 31;
    int warp = tidg >> 5;                          // 0..NWARP-1

    // squared weights in half2, lane's 8 dims x 4 perspectives (16 regs)
    __half2 w2r[N_PERS][4];
    {
        const float4* mw4 = reinterpret_cast<const float4*>(mw);
        #pragma unroll
        for (int p = 0; p < N_PERS; p++) {
            float4 wa = __ldg(mw4 + p * 64 + 2 * lane);
            float4 wb = __ldg(mw4 + p * 64 + 2 * lane + 1);
            w2r[p][0] = __floats2half2_rn(wa.x * wa.x, wa.y * wa.y);
            w2r[p][1] = __floats2half2_rn(wa.z * wa.z, wa.w * wa.w);
            w2r[p][2] = __floats2half2_rn(wb.x * wb.x, wb.y * wb.y);
            w2r[p][3] = __floats2half2_rn(wb.z * wb.z, wb.w * wb.w);
        }
    }

    const float4 z = make_float4(0.f, 0.f, 0.f, 0.f);
    int fidx = tidg;

    // pipeline: preload iteration-0 edge indices
    int e0 = warp;
    int i_n = (e0 < E_FULL) ? __ldg(fe + e0) : 0;
    int j_n = (e0 < E_FULL) ? __ldg(fe + E_FULL + e0) : 0;

    for (int it = 0; it < MAIN_ITERS; it++) {
        // ---- two streaming zero-stores (hidden under edge load latency) ----
        if (fidx < OUT_F4) __stcs(out4 + fidx, z);
        int f2i = fidx + NT;
        if (f2i < OUT_F4) __stcs(out4 + f2i, z);
        fidx += 2 * NT;

        int e = warp + it * NWARP;
        if (e >= E_FULL) continue;
        int i = i_n, j = j_n;

        // all independent loads first: table rows + broadcast rinv
        uint2 qi = __ldg(g_qtab + i * 32 + lane);
        uint2 qj = __ldg(g_qtab + j * 32 + lane);
        float4 ri = __ldg(g_rinv4 + i);            // warp-uniform broadcast
        float4 rj = __ldg(g_rinv4 + j);

        // prefetch next iteration's indices (breaks fe->qtab serial chain)
        int en = e + NWARP;
        if (en < E_FULL) {
            i_n = __ldg(fe + en);
            j_n = __ldg(fe + E_FULL + en);
        }

        // hw fp8x2 -> half2 decode (8 cvts)
        __half2 hi0 = fp8x2_to_h2((unsigned short)(qi.x & 0xffffu));
        __half2 hi1 = fp8x2_to_h2((unsigned short)(qi.x >> 16));
        __half2 hi2 = fp8x2_to_h2((unsigned short)(qi.y & 0xffffu));
        __half2 hi3 = fp8x2_to_h2((unsigned short)(qi.y >> 16));
        __half2 hj0 = fp8x2_to_h2((unsigned short)(qj.x & 0xffffu));
        __half2 hj1 = fp8x2_to_h2((unsigned short)(qj.x >> 16));
        __half2 hj2 = fp8x2_to_h2((unsigned short)(qj.y & 0xffffu));
        __half2 hj3 = fp8x2_to_h2((unsigned short)(qj.y >> 16));

        __half2 pr0 = __hmul2(hi0, hj0);
        __half2 pr1 = __hmul2(hi1, hj1);
        __half2 pr2 = __hmul2(hi2, hj2);
        __half2 pr3 = __hmul2(hi3, hj3);

        __half2 a0 = __hmul2(pr0, w2r[0][0]);
        __half2 a1 = __hmul2(pr0, w2r[1][0]);
        __half2 a2 = __hmul2(pr0, w2r[2][0]);
        __half2 a3 = __hmul2(pr0, w2r[3][0]);
        a0 = __hfma2(pr1, w2r[0][1], a0); a1 = __hfma2(pr1, w2r[1][1], a1);
        a2 = __hfma2(pr1, w2r[2][1], a2); a3 = __hfma2(pr1, w2r[3][1], a3);
        a0 = __hfma2(pr2, w2r[0][2], a0); a1 = __hfma2(pr2, w2r[1][2], a1);
        a2 = __hfma2(pr2, w2r[2][2], a2); a3 = __hfma2(pr2, w2r[3][2], a3);
        a0 = __hfma2(pr3, w2r[0][3], a0); a1 = __hfma2(pr3, w2r[1][3], a1);
        a2 = __hfma2(pr3, w2r[2][3], a2); a3 = __hfma2(pr3, w2r[3][3], a3);

        // fold rinv per lane (reordered but mathematically identical sum)
        float s = (__low2float(a0) + __high2float(a0)) * (ri.x * rj.x)
                + (__low2float(a1) + __high2float(a1)) * (ri.y * rj.y)
                + (__low2float(a2) + __high2float(a2)) * (ri.z * rj.z)
                + (__low2float(a3) + __high2float(a3)) * (ri.w * rj.w);

        // single 5-shuffle reduction
        s += __shfl_xor_sync(0xffffffffu, s, 16);
        s += __shfl_xor_sync(0xffffffffu, s, 8);
        s += __shfl_xor_sync(0xffffffffu, s, 4);
        s += __shfl_xor_sync(0xffffffffu, s, 2);
        s += __shfl_xor_sync(0xffffffffu, s, 1);
        float simA = 0.25f * s;

        if (simA > SCREEN && i != j)
            exact_edge(i, j, lane, x, mw, smap);   // warp-uniform rare path
    }
}

// ---------------- scatter: raw edges + hits + lazy bitmap clear ----------------
__global__ void scatter_kernel(const int* __restrict__ re, float* __restrict__ out) {
    int t = blockIdx.x * blockDim.x + threadIdx.x;   // exactly E_RAW threads
    int r = __ldg(re + t);
    int c = __ldg(re + E_RAW + t);
    atomicAdd(out + (size_t)r * N_TOTAL + c, 1.0f - LAMB1);
    if (t < g_nhits) {
        atomicAdd(out + (size_t)g_hit_off[t], g_hit_val[t]);
        g_bitmap[g_hit_word[t]] = 0;                 // keep replay-deterministic
    }
}

// ---------------- launch ----------------
extern "C" void kernel_launch(void* const* d_in, const int* in_sizes, int n_in,
                              void* d_out, int out_size) {
    const float* x      = (const float*)d_in[0];   // [8192, 256]
    const float* mw     = (const float*)d_in[1];   // [4, 256]
    const int*   batch  = (const int*)  d_in[2];   // [8192]
    const int*   smap   = (const int*)  d_in[3];   // [8192]
    const int*   belong = (const int*)  d_in[4];   // [256]
    const float* score  = (const float*)d_in[5];   // [256]
    const int*   fe     = (const int*)  d_in[6];   // [2, 262144]
    const int*   re     = (const int*)  d_in[7];   // [2, 262144]
    float* out = (float*)d_out;                    // [8192, 8192]

    prep_kernel<<<513, 256>>>(x, mw, score, belong, batch);
    main_kernel<<<MAIN_BLOCKS, 256>>>(x, mw, fe, smap,
                                      reinterpret_cast<float4*>(out));
    scatter_kernel<<<E_RAW / 256, 256>>>(re, out);
}